// round 6
// baseline (speedup 1.0000x reference)
#include <cuda_runtime.h>
#include <cstdint>

// ---------------- problem constants ----------------
#define BB 4
#define HH 16
#define NSEQ 8192
#define DD 64
#define EE 64
#define BH (BB*HH)                       // 64
#define OUTG_ELEMS (BH*NSEQ*EE)          // 33554432
#define KV_ELEMS (BH*DD*EE)              // 262144
#define NORM_ELEMS (BH*DD)               // 4096

#define CHUNKS 32
#define ROWS_PER_BLOCK 256
#define TILE 64
#define NTILES 4
#define THREADS 128

#define STRIDE 68                        // floats per smem row (pad 4 -> ldmatrix conflict-free)
// float offsets inside dynamic smem (single-buffered)
#define F_SQ 0                           // converted Q tile : 64 rows
#define F_SK (64*STRIDE)                 // converted K tile : 64 rows
#define F_B1 (2*64*STRIDE)               // past_kv^T (tf32) + norm row 64 : 72 rows
#define F_VT (F_B1 + 72*STRIDE)          // v'^T (tf32) + ones row 64      : 72 rows
#define SMEM_FLOATS (F_VT + 72*STRIDE)   // 18496
#define SMEM_BYTES (SMEM_FLOATS*4)       // 73984 -> 3 blocks/SM

// ---------------- helpers ----------------
__device__ __forceinline__ uint32_t smem_u32(const void* p) {
    uint32_t a;
    asm("{ .reg .u64 t; cvta.to.shared.u64 t, %1; cvt.u32.u64 %0, t; }" : "=r"(a) : "l"(p));
    return a;
}
__device__ __forceinline__ uint32_t cvt_tf32(float x) {
    uint32_t u;
    asm("cvt.rna.tf32.f32 %0, %1;" : "=r"(u) : "f"(x));
    return u;
}
__device__ __forceinline__ float elu1(float x) { return (x > 0.f) ? (x + 1.f) : __expf(x); }
__device__ __forceinline__ void mma8(float* d, uint32_t a0, uint32_t a1, uint32_t a2, uint32_t a3,
                                     uint32_t b0, uint32_t b1) {
    asm volatile("mma.sync.aligned.m16n8k8.row.col.f32.tf32.tf32.f32 "
                 "{%0,%1,%2,%3}, {%4,%5,%6,%7}, {%8,%9}, {%0,%1,%2,%3};"
                 : "+f"(d[0]), "+f"(d[1]), "+f"(d[2]), "+f"(d[3])
                 : "r"(a0), "r"(a1), "r"(a2), "r"(a3), "r"(b0), "r"(b1));
}
__device__ __forceinline__ void ldsm4(uint32_t* r, uint32_t addr) {
    asm volatile("ldmatrix.sync.aligned.m8n8.x4.shared.b16 {%0,%1,%2,%3}, [%4];"
                 : "=r"(r[0]), "=r"(r[1]), "=r"(r[2]), "=r"(r[3]) : "r"(addr));
}
__device__ __forceinline__ void ldsm2(uint32_t* r, uint32_t addr) {
    asm volatile("ldmatrix.sync.aligned.m8n8.x2.shared.b16 {%0,%1}, [%2];"
                 : "=r"(r[0]), "=r"(r[1]) : "r"(addr));
}

__global__ void __launch_bounds__(THREADS, 3)
fw_kernel(const float* __restrict__ keys,
          const float* __restrict__ values,
          const float* __restrict__ queries,
          const float* __restrict__ outp,
          const float* __restrict__ past_kv,
          const float* __restrict__ past_norm,
          const float* __restrict__ head_gates,
          float* __restrict__ dout)
{
    extern __shared__ float smem[];
    const uint32_t sbase = smem_u32(smem);
    const int tid  = threadIdx.x;
    const int lane = tid & 31;
    const int w    = tid >> 5;           // warp 0..3
    const int bh   = blockIdx.y;

    const uint32_t uQ  = sbase + (uint32_t)F_SQ * 4u;
    const uint32_t uK  = sbase + (uint32_t)F_SK * 4u;
    const uint32_t uB1 = sbase + (uint32_t)F_B1 * 4u;
    const uint32_t uVT = sbase + (uint32_t)F_VT * 4u;

    // ---- stage B1 = past_kv^T (tf32) + norm row; VT constant rows ----
    {
        const float* pkv = past_kv + (size_t)bh * (DD*EE);
        for (int i = tid; i < DD*EE; i += THREADS) {
            int d = i >> 6, e = i & 63;
            smem[F_B1 + e*STRIDE + d] = __uint_as_float(cvt_tf32(pkv[i]));
        }
        if (tid < 64)
            smem[F_B1 + 64*STRIDE + tid] = __uint_as_float(cvt_tf32(past_norm[bh*DD + tid]));
        for (int i = tid; i < 7*STRIDE; i += THREADS) {
            smem[F_B1 + 65*STRIDE + i] = 0.0f;
            smem[F_VT + 65*STRIDE + i] = 0.0f;
        }
        for (int i = tid; i < 64; i += THREADS)
            smem[F_VT + 64*STRIDE + i] = 1.0f;   // ones row -> new_norm column
    }

    float gate;
    {
        float hg = head_gates[bh & (HH-1)];
        gate = 1.0f / (1.0f + __expf(-hg));
    }
    const float omg = 1.0f - gate;

    const long rowbase = (long)bh * NSEQ + (long)blockIdx.x * ROWS_PER_BLOCK;

    float d2[9][4];
    #pragma unroll
    for (int n = 0; n < 9; ++n)
        #pragma unroll
        for (int c = 0; c < 4; ++c) d2[n][c] = 0.f;

    const bool isQ = (w < 2);
    const int rloc = 32 * (w & 1);       // local base row within Q-half or K-half
    const uint32_t uA = isQ ? uQ : uK;

    // ldmatrix lane-address components (constant per thread)
    const uint32_t a_row_off = (uint32_t)((lane & 7) + (lane & 8));      // row within 16-row A block
    const uint32_t a_col_off = (uint32_t)((lane >> 4) << 2);             // +0 or +4 (k)
    const uint32_t b_n_off   = (uint32_t)(((lane >> 4) << 3) + (lane & 7)); // n within 16-row B pair
    const uint32_t b_col_off = (uint32_t)(((lane >> 3) & 1) << 2);       // +0 or +4 (k)

    for (int t = 0; t < NTILES; ++t) {
        const long rowb = rowbase + (long)t * TILE;

        // ---- load raw Q/K -> regs -> elu+tf32 -> smem (no cp.async, no LDS pass) ----
        {
            const float4* qs = reinterpret_cast<const float4*>(queries + rowb * DD);
            const float4* ks = reinterpret_cast<const float4*>(keys + rowb * DD);
            #pragma unroll
            for (int b = 0; b < 2; ++b) {
                float4 qv[4], kv[4];
                #pragma unroll
                for (int i = 0; i < 4; ++i) {
                    int idx = b*512 + i*128 + tid;
                    qv[i] = qs[idx];
                    kv[i] = ks[idx];
                }
                #pragma unroll
                for (int i = 0; i < 4; ++i) {
                    int idx = b*512 + i*128 + tid;
                    int row = idx >> 4, seg = idx & 15;
                    float4 v = qv[i];
                    v.x = __uint_as_float(cvt_tf32(elu1(v.x)));
                    v.y = __uint_as_float(cvt_tf32(elu1(v.y)));
                    v.z = __uint_as_float(cvt_tf32(elu1(v.z)));
                    v.w = __uint_as_float(cvt_tf32(elu1(v.w)));
                    *reinterpret_cast<float4*>(smem + F_SQ + row*STRIDE + seg*4) = v;
                    float4 u = kv[i];
                    u.x = __uint_as_float(cvt_tf32(elu1(u.x)));
                    u.y = __uint_as_float(cvt_tf32(elu1(u.y)));
                    u.z = __uint_as_float(cvt_tf32(elu1(u.z)));
                    u.w = __uint_as_float(cvt_tf32(elu1(u.w)));
                    *reinterpret_cast<float4*>(smem + F_SK + row*STRIDE + seg*4) = u;
                }
            }
        }
        __syncthreads();

        // ---- GEMM1: D1 = [Q;K] x B1  (N=72, col 64 = denominator) ----
        float d1[2][9][4];
        #pragma unroll
        for (int mt = 0; mt < 2; ++mt)
            #pragma unroll
            for (int n = 0; n < 9; ++n)
                #pragma unroll
                for (int c = 0; c < 4; ++c) d1[mt][n][c] = 0.f;

        #pragma unroll
        for (int ks8 = 0; ks8 < 8; ++ks8) {
            const uint32_t kcol = (uint32_t)(8*ks8);
            uint32_t bf[9][2];
            #pragma unroll
            for (int j = 0; j < 4; ++j) {
                uint32_t r4[4];
                uint32_t n = 16u*j + b_n_off;
                ldsm4(r4, uB1 + (n*STRIDE + kcol + b_col_off)*4u);
                bf[2*j][0] = r4[0]; bf[2*j][1] = r4[1];
                bf[2*j+1][0] = r4[2]; bf[2*j+1][1] = r4[3];
            }
            {
                uint32_t r2[2];
                uint32_t n = 64u + (lane & 7);
                ldsm2(r2, uB1 + (n*STRIDE + kcol + b_col_off)*4u);
                bf[8][0] = r2[0]; bf[8][1] = r2[1];
            }
            #pragma unroll
            for (int mt = 0; mt < 2; ++mt) {
                uint32_t a[4];
                uint32_t row = (uint32_t)(rloc + 16*mt) + a_row_off;
                ldsm4(a, uA + (row*STRIDE + kcol + a_col_off)*4u);
                #pragma unroll
                for (int nt = 0; nt < 9; ++nt)
                    mma8(d1[mt][nt], a[0], a[1], a[2], a[3], bf[nt][0], bf[nt][1]);
            }
        }

        // ---- epilogue ----
        #pragma unroll
        for (int mt = 0; mt < 2; ++mt) {
            float den0 = __shfl_sync(0xffffffffu, d1[mt][8][0], lane & 28);
            float den1 = __shfl_sync(0xffffffffu, d1[mt][8][2], lane & 28);
            float r0 = 1.0f / fmaxf(den0, 1e-10f);
            float r1 = 1.0f / fmaxf(den1, 1e-10f);
            int lrow = rloc + 16*mt + (lane >> 2);   // local row in tile
            int ec = lane & 3;
            if (isQ) {
                float c0 = r0 * omg, c1 = r1 * omg;
                const float2* o0 = (const float2*)(outp + (size_t)(rowb + lrow) * EE);
                const float2* o1 = (const float2*)(outp + (size_t)(rowb + lrow + 8) * EE);
                float2* g0 = (float2*)(dout + (size_t)(rowb + lrow) * EE);
                float2* g1 = (float2*)(dout + (size_t)(rowb + lrow + 8) * EE);
                #pragma unroll
                for (int nt = 0; nt < 8; ++nt) {
                    float2 a = o0[4*nt + ec];
                    float2 b = o1[4*nt + ec];
                    float2 ra, rb;
                    ra.x = a.x * gate + d1[mt][nt][0] * c0;
                    ra.y = a.y * gate + d1[mt][nt][1] * c0;
                    rb.x = b.x * gate + d1[mt][nt][2] * c1;
                    rb.y = b.y * gate + d1[mt][nt][3] * c1;
                    g0[4*nt + ec] = ra;
                    g1[4*nt + ec] = rb;
                }
            } else {
                const float2* v0 = (const float2*)(values + (size_t)(rowb + lrow) * EE);
                const float2* v1 = (const float2*)(values + (size_t)(rowb + lrow + 8) * EE);
                #pragma unroll
                for (int nt = 0; nt < 8; ++nt) {
                    float2 a = v0[4*nt + ec];
                    float2 b = v1[4*nt + ec];
                    int e = 8*nt + 2*ec;
                    float p00 = a.x - d1[mt][nt][0] * r0;
                    float p01 = a.y - d1[mt][nt][1] * r0;
                    float p10 = b.x - d1[mt][nt][2] * r1;
                    float p11 = b.y - d1[mt][nt][3] * r1;
                    smem[F_VT + e*STRIDE + lrow]         = __uint_as_float(cvt_tf32(p00));
                    smem[F_VT + (e+1)*STRIDE + lrow]     = __uint_as_float(cvt_tf32(p01));
                    smem[F_VT + e*STRIDE + lrow + 8]     = __uint_as_float(cvt_tf32(p10));
                    smem[F_VT + (e+1)*STRIDE + lrow + 8] = __uint_as_float(cvt_tf32(p11));
                }
            }
        }
        __syncthreads();

        // ---- GEMM2: D2 += k^T x v'  (N=72, col 64 = norm sums) ----
        #pragma unroll
        for (int ks8 = 0; ks8 < 8; ++ks8) {
            const uint32_t kcol = (uint32_t)(8*ks8);
            uint32_t bf[9][2];
            #pragma unroll
            for (int j = 0; j < 4; ++j) {
                uint32_t r4[4];
                uint32_t n = 16u*j + b_n_off;
                ldsm4(r4, uVT + (n*STRIDE + kcol + b_col_off)*4u);
                bf[2*j][0] = r4[0]; bf[2*j][1] = r4[1];
                bf[2*j+1][0] = r4[2]; bf[2*j+1][1] = r4[3];
            }
            {
                uint32_t r2[2];
                uint32_t n = 64u + (lane & 7);
                ldsm2(r2, uVT + (n*STRIDE + kcol + b_col_off)*4u);
                bf[8][0] = r2[0]; bf[8][1] = r2[1];
            }
            // A = k^T : scalar transposed reads (conflict-free by stride-68 stagger)
            const float* ap = smem + F_SK + (8*ks8 + (lane&3))*STRIDE + 16*w + (lane>>2);
            uint32_t a0 = __float_as_uint(ap[0]);
            uint32_t a1 = __float_as_uint(ap[8]);
            uint32_t a2 = __float_as_uint(ap[4*STRIDE]);
            uint32_t a3 = __float_as_uint(ap[4*STRIDE + 8]);
            #pragma unroll
            for (int nt = 0; nt < 9; ++nt)
                mma8(d2[nt], a0, a1, a2, a3, bf[nt][0], bf[nt][1]);
        }
        __syncthreads();   // buffers free for next tile
    }

    // ---- flush D2: new_kv (+past via memcpy seed) and new_norm ----
    {
        float* okv = dout + OUTG_ELEMS + (size_t)bh * (DD*EE);
        int dr = 16*w + (lane >> 2);
        #pragma unroll
        for (int nt = 0; nt < 8; ++nt) {
            int e = 8*nt + 2*(lane & 3);
            atomicAdd(okv + dr*EE + e,        d2[nt][0]);
            atomicAdd(okv + dr*EE + e + 1,    d2[nt][1]);
            atomicAdd(okv + (dr+8)*EE + e,    d2[nt][2]);
            atomicAdd(okv + (dr+8)*EE + e+1,  d2[nt][3]);
        }
        if ((lane & 3) == 0) {
            float* on = dout + OUTG_ELEMS + KV_ELEMS + bh*DD;
            atomicAdd(on + dr,     d2[8][0]);
            atomicAdd(on + dr + 8, d2[8][2]);
        }
    }
}

extern "C" void kernel_launch(void* const* d_in, const int* in_sizes, int n_in,
                              void* d_out, int out_size)
{
    const float* keys      = (const float*)d_in[0];
    const float* values    = (const float*)d_in[1];
    const float* queries   = (const float*)d_in[2];
    const float* outp      = (const float*)d_in[3];
    const float* past_kv   = (const float*)d_in[4];
    const float* past_norm = (const float*)d_in[5];
    const float* gates     = (const float*)d_in[6];
    float* dout = (float*)d_out;

    // Seed new_kv / new_norm output regions (atomics add partials on top)
    cudaMemcpyAsync(dout + OUTG_ELEMS, past_kv, KV_ELEMS * sizeof(float),
                    cudaMemcpyDeviceToDevice);
    cudaMemcpyAsync(dout + OUTG_ELEMS + KV_ELEMS, past_norm, NORM_ELEMS * sizeof(float),
                    cudaMemcpyDeviceToDevice);

    cudaFuncSetAttribute(fw_kernel, cudaFuncAttributeMaxDynamicSharedMemorySize, SMEM_BYTES);

    dim3 grid(CHUNKS, BH);
    fw_kernel<<<grid, THREADS, SMEM_BYTES>>>(keys, values, queries, outp,
                                             past_kv, past_norm, gates, dout);
}

// round 7
// speedup vs baseline: 1.2001x; 1.2001x over previous
#include <cuda_runtime.h>
#include <cstdint>

// ---------------- problem constants ----------------
#define BB 4
#define HH 16
#define NSEQ 8192
#define DD 64
#define EE 64
#define BH (BB*HH)                       // 64
#define OUTG_ELEMS (BH*NSEQ*EE)          // 33554432
#define KV_ELEMS (BH*DD*EE)              // 262144
#define NORM_ELEMS (BH*DD)               // 4096

#define CHUNKS 32
#define ROWS_PER_BLOCK 256
#define TILE 64
#define NTILES 4
#define THREADS 128

#define STRIDE 68                        // floats per smem row (pad 4 -> conflict-free ldmatrix)
// float offsets inside dynamic smem
#define F_SQ0 0                          // RAW Q tile, double buffered (elu applied in regs)
#define F_SK0 (2*64*STRIDE)              // RAW K tile, double buffered
#define F_B1  (4*64*STRIDE)              // past_kv^T (tf32) + norm row 64 : 72 rows
#define F_VT  (F_B1 + 72*STRIDE)         // v'^T (tf32) + ones row 64      : 72 rows
#define SMEM_FLOATS (F_VT + 72*STRIDE)   // 27200
#define SMEM_BYTES (SMEM_FLOATS*4)       // 108800 -> 2 blocks/SM

// ---------------- helpers ----------------
__device__ __forceinline__ uint32_t smem_u32(const void* p) {
    uint32_t a;
    asm("{ .reg .u64 t; cvta.to.shared.u64 t, %1; cvt.u32.u64 %0, t; }" : "=r"(a) : "l"(p));
    return a;
}
__device__ __forceinline__ uint32_t cvt_tf32(float x) {
    uint32_t u;
    asm("cvt.rna.tf32.f32 %0, %1;" : "=r"(u) : "f"(x));
    return u;
}
__device__ __forceinline__ float elu1(float x) { return (x > 0.f) ? (x + 1.f) : __expf(x); }
// elementwise elu+tf32 on a raw fp32 bit-pattern register (layout-agnostic)
__device__ __forceinline__ uint32_t elu_tf32_u(uint32_t raw) {
    return cvt_tf32(elu1(__uint_as_float(raw)));
}
__device__ __forceinline__ void cp16(uint32_t dst, const void* src) {
    asm volatile("cp.async.cg.shared.global [%0], [%1], 16;" :: "r"(dst), "l"(src));
}
__device__ __forceinline__ void mma8(float* d, uint32_t a0, uint32_t a1, uint32_t a2, uint32_t a3,
                                     uint32_t b0, uint32_t b1) {
    asm volatile("mma.sync.aligned.m16n8k8.row.col.f32.tf32.tf32.f32 "
                 "{%0,%1,%2,%3}, {%4,%5,%6,%7}, {%8,%9}, {%0,%1,%2,%3};"
                 : "+f"(d[0]), "+f"(d[1]), "+f"(d[2]), "+f"(d[3])
                 : "r"(a0), "r"(a1), "r"(a2), "r"(a3), "r"(b0), "r"(b1));
}
__device__ __forceinline__ void ldsm4(uint32_t* r, uint32_t addr) {
    asm volatile("ldmatrix.sync.aligned.m8n8.x4.shared.b16 {%0,%1,%2,%3}, [%4];"
                 : "=r"(r[0]), "=r"(r[1]), "=r"(r[2]), "=r"(r[3]) : "r"(addr));
}
__device__ __forceinline__ void ldsm2(uint32_t* r, uint32_t addr) {
    asm volatile("ldmatrix.sync.aligned.m8n8.x2.shared.b16 {%0,%1}, [%2];"
                 : "=r"(r[0]), "=r"(r[1]) : "r"(addr));
}

__global__ void __launch_bounds__(THREADS)
fw_kernel(const float* __restrict__ keys,
          const float* __restrict__ values,
          const float* __restrict__ queries,
          const float* __restrict__ outp,
          const float* __restrict__ past_kv,
          const float* __restrict__ past_norm,
          const float* __restrict__ head_gates,
          float* __restrict__ dout)
{
    extern __shared__ float smem[];
    const uint32_t sbase = smem_u32(smem);
    const int tid  = threadIdx.x;
    const int lane = tid & 31;
    const int w    = tid >> 5;           // warp 0..3
    const int bh   = blockIdx.y;

    const uint32_t uB1 = sbase + (uint32_t)F_B1 * 4u;
    const uint32_t uVT = sbase + (uint32_t)F_VT * 4u;

    // ---- stage B1 = past_kv^T (tf32) + norm row; VT constant rows ----
    {
        const float* pkv = past_kv + (size_t)bh * (DD*EE);
        for (int i = tid; i < DD*EE; i += THREADS) {
            int d = i >> 6, e = i & 63;
            smem[F_B1 + e*STRIDE + d] = __uint_as_float(cvt_tf32(pkv[i]));
        }
        if (tid < 64)
            smem[F_B1 + 64*STRIDE + tid] = __uint_as_float(cvt_tf32(past_norm[bh*DD + tid]));
        for (int i = tid; i < 7*STRIDE; i += THREADS) {
            smem[F_B1 + 65*STRIDE + i] = 0.0f;
            smem[F_VT + 65*STRIDE + i] = 0.0f;
        }
        for (int i = tid; i < 64; i += THREADS)
            smem[F_VT + 64*STRIDE + i] = 1.0f;   // ones row -> new_norm column
    }

    float gate;
    {
        float hg = head_gates[bh & (HH-1)];
        gate = 1.0f / (1.0f + __expf(-hg));
    }
    const float omg = 1.0f - gate;

    const long rowbase = (long)bh * NSEQ + (long)blockIdx.x * ROWS_PER_BLOCK;

    auto stage = [&](int buf, long rowb) {
        const float* qs = queries + rowb * DD;
        const float* ks = keys    + rowb * DD;
        uint32_t qd = sbase + (uint32_t)(F_SQ0 + buf*(64*STRIDE)) * 4u;
        uint32_t kd = sbase + (uint32_t)(F_SK0 + buf*(64*STRIDE)) * 4u;
        #pragma unroll
        for (int j = 0; j < 8; ++j) {
            int idx = j*THREADS + tid;
            int row = idx >> 4, seg = idx & 15;
            cp16(qd + (uint32_t)row*(STRIDE*4) + seg*16, qs + row*DD + seg*4);
            cp16(kd + (uint32_t)row*(STRIDE*4) + seg*16, ks + row*DD + seg*4);
        }
        asm volatile("cp.async.commit_group;" ::: "memory");
    };

    stage(0, rowbase);

    float d2[9][4];
    #pragma unroll
    for (int n = 0; n < 9; ++n)
        #pragma unroll
        for (int c = 0; c < 4; ++c) d2[n][c] = 0.f;

    const bool isQ = (w < 2);
    const int rloc = 32 * (w & 1);       // local base row within Q-half or K-half

    // ldmatrix lane-address components (constant per thread)
    const uint32_t a_row_off = (uint32_t)((lane & 7) + (lane & 8));         // row within 16-row A block
    const uint32_t a_col_off = (uint32_t)((lane >> 4) << 2);                // +0 or +4 (k)
    const uint32_t b_n_off   = (uint32_t)(((lane >> 4) << 3) + (lane & 7)); // n within 16-row B pair
    const uint32_t b_col_off = (uint32_t)(((lane >> 3) & 1) << 2);          // +0 or +4 (k)

    for (int t = 0; t < NTILES; ++t) {
        const long rowb = rowbase + (long)t * TILE;
        if (t + 1 < NTILES) {
            stage((t+1) & 1, rowb + TILE);
            asm volatile("cp.async.wait_group 1;" ::: "memory");
        } else {
            asm volatile("cp.async.wait_group 0;" ::: "memory");
        }
        __syncthreads();

        const uint32_t uQ = sbase + (uint32_t)(F_SQ0 + (t & 1)*(64*STRIDE)) * 4u;
        const uint32_t uK = sbase + (uint32_t)(F_SK0 + (t & 1)*(64*STRIDE)) * 4u;
        const uint32_t uA = isQ ? uQ : uK;

        // ---- GEMM1: D1 = elu([Q;K]) x B1  (N=72, col 64 = denominator) ----
        float d1[2][9][4];
        #pragma unroll
        for (int mt = 0; mt < 2; ++mt)
            #pragma unroll
            for (int n = 0; n < 9; ++n)
                #pragma unroll
                for (int c = 0; c < 4; ++c) d1[mt][n][c] = 0.f;

        #pragma unroll
        for (int ks8 = 0; ks8 < 8; ++ks8) {
            const uint32_t kcol = (uint32_t)(8*ks8);
            uint32_t bf[9][2];
            #pragma unroll
            for (int j = 0; j < 4; ++j) {
                uint32_t r4[4];
                uint32_t n = 16u*j + b_n_off;
                ldsm4(r4, uB1 + (n*STRIDE + kcol + b_col_off)*4u);
                bf[2*j][0] = r4[0]; bf[2*j][1] = r4[1];
                bf[2*j+1][0] = r4[2]; bf[2*j+1][1] = r4[3];
            }
            {
                uint32_t r2[2];
                uint32_t n = 64u + (lane & 7);
                ldsm2(r2, uB1 + (n*STRIDE + kcol + b_col_off)*4u);
                bf[8][0] = r2[0]; bf[8][1] = r2[1];
            }
            #pragma unroll
            for (int mt = 0; mt < 2; ++mt) {
                uint32_t a[4];
                uint32_t row = (uint32_t)(rloc + 16*mt) + a_row_off;
                ldsm4(a, uA + (row*STRIDE + kcol + a_col_off)*4u);
                a[0] = elu_tf32_u(a[0]);   // raw -> elu+tf32 in regs (elementwise)
                a[1] = elu_tf32_u(a[1]);
                a[2] = elu_tf32_u(a[2]);
                a[3] = elu_tf32_u(a[3]);
                #pragma unroll
                for (int nt = 0; nt < 9; ++nt)
                    mma8(d1[mt][nt], a[0], a[1], a[2], a[3], bf[nt][0], bf[nt][1]);
            }
        }

        // ---- epilogue ----
        #pragma unroll
        for (int mt = 0; mt < 2; ++mt) {
            float den0 = __shfl_sync(0xffffffffu, d1[mt][8][0], lane & 28);
            float den1 = __shfl_sync(0xffffffffu, d1[mt][8][2], lane & 28);
            float r0 = 1.0f / fmaxf(den0, 1e-10f);
            float r1 = 1.0f / fmaxf(den1, 1e-10f);
            int lrow = rloc + 16*mt + (lane >> 2);   // local row in tile
            int ec = lane & 3;
            if (isQ) {
                float c0 = r0 * omg, c1 = r1 * omg;
                const float2* o0 = (const float2*)(outp + (size_t)(rowb + lrow) * EE);
                const float2* o1 = (const float2*)(outp + (size_t)(rowb + lrow + 8) * EE);
                float2* g0 = (float2*)(dout + (size_t)(rowb + lrow) * EE);
                float2* g1 = (float2*)(dout + (size_t)(rowb + lrow + 8) * EE);
                #pragma unroll
                for (int nt = 0; nt < 8; ++nt) {
                    float2 a = o0[4*nt + ec];
                    float2 b = o1[4*nt + ec];
                    float2 ra, rb;
                    ra.x = a.x * gate + d1[mt][nt][0] * c0;
                    ra.y = a.y * gate + d1[mt][nt][1] * c0;
                    rb.x = b.x * gate + d1[mt][nt][2] * c1;
                    rb.y = b.y * gate + d1[mt][nt][3] * c1;
                    g0[4*nt + ec] = ra;
                    g1[4*nt + ec] = rb;
                }
            } else {
                const float2* v0 = (const float2*)(values + (size_t)(rowb + lrow) * EE);
                const float2* v1 = (const float2*)(values + (size_t)(rowb + lrow + 8) * EE);
                #pragma unroll
                for (int nt = 0; nt < 8; ++nt) {
                    float2 a = v0[4*nt + ec];
                    float2 b = v1[4*nt + ec];
                    int e = 8*nt + 2*ec;
                    float p00 = a.x - d1[mt][nt][0] * r0;
                    float p01 = a.y - d1[mt][nt][1] * r0;
                    float p10 = b.x - d1[mt][nt][2] * r1;
                    float p11 = b.y - d1[mt][nt][3] * r1;
                    smem[F_VT + e*STRIDE + lrow]         = __uint_as_float(cvt_tf32(p00));
                    smem[F_VT + (e+1)*STRIDE + lrow]     = __uint_as_float(cvt_tf32(p01));
                    smem[F_VT + e*STRIDE + lrow + 8]     = __uint_as_float(cvt_tf32(p10));
                    smem[F_VT + (e+1)*STRIDE + lrow + 8] = __uint_as_float(cvt_tf32(p11));
                }
            }
        }
        __syncthreads();

        // ---- GEMM2: D2 += elu(k)^T x v'  (N=72, col 64 = norm sums) ----
        #pragma unroll
        for (int ks8 = 0; ks8 < 8; ++ks8) {
            const uint32_t kcol = (uint32_t)(8*ks8);
            uint32_t bf[9][2];
            #pragma unroll
            for (int j = 0; j < 4; ++j) {
                uint32_t r4[4];
                uint32_t n = 16u*j + b_n_off;
                ldsm4(r4, uVT + (n*STRIDE + kcol + b_col_off)*4u);
                bf[2*j][0] = r4[0]; bf[2*j][1] = r4[1];
                bf[2*j+1][0] = r4[2]; bf[2*j+1][1] = r4[3];
            }
            {
                uint32_t r2[2];
                uint32_t n = 64u + (lane & 7);
                ldsm2(r2, uVT + (n*STRIDE + kcol + b_col_off)*4u);
                bf[8][0] = r2[0]; bf[8][1] = r2[1];
            }
            // A = elu(k)^T : scalar transposed reads from RAW K + elu in regs
            const float* ap = reinterpret_cast<const float*>(smem) +
                              ((uK - sbase) >> 2) + (8*ks8 + (lane&3))*STRIDE + 16*w + (lane>>2);
            uint32_t a0 = elu_tf32_u(__float_as_uint(ap[0]));
            uint32_t a1 = elu_tf32_u(__float_as_uint(ap[8]));
            uint32_t a2 = elu_tf32_u(__float_as_uint(ap[4*STRIDE]));
            uint32_t a3 = elu_tf32_u(__float_as_uint(ap[4*STRIDE + 8]));
            #pragma unroll
            for (int nt = 0; nt < 9; ++nt)
                mma8(d2[nt], a0, a1, a2, a3, bf[nt][0], bf[nt][1]);
        }
        __syncthreads();   // raw K + VT reads done before next stage/epilogue overwrite
    }

    // ---- flush D2: new_kv (+past via memcpy seed) and new_norm ----
    {
        float* okv = dout + OUTG_ELEMS + (size_t)bh * (DD*EE);
        int dr = 16*w + (lane >> 2);
        #pragma unroll
        for (int nt = 0; nt < 8; ++nt) {
            int e = 8*nt + 2*(lane & 3);
            atomicAdd(okv + dr*EE + e,        d2[nt][0]);
            atomicAdd(okv + dr*EE + e + 1,    d2[nt][1]);
            atomicAdd(okv + (dr+8)*EE + e,    d2[nt][2]);
            atomicAdd(okv + (dr+8)*EE + e+1,  d2[nt][3]);
        }
        if ((lane & 3) == 0) {
            float* on = dout + OUTG_ELEMS + KV_ELEMS + bh*DD;
            atomicAdd(on + dr,     d2[8][0]);
            atomicAdd(on + dr + 8, d2[8][2]);
        }
    }
}

extern "C" void kernel_launch(void* const* d_in, const int* in_sizes, int n_in,
                              void* d_out, int out_size)
{
    const float* keys      = (const float*)d_in[0];
    const float* values    = (const float*)d_in[1];
    const float* queries   = (const float*)d_in[2];
    const float* outp      = (const float*)d_in[3];
    const float* past_kv   = (const float*)d_in[4];
    const float* past_norm = (const float*)d_in[5];
    const float* gates     = (const float*)d_in[6];
    float* dout = (float*)d_out;

    // Seed new_kv / new_norm output regions (atomics add partials on top)
    cudaMemcpyAsync(dout + OUTG_ELEMS, past_kv, KV_ELEMS * sizeof(float),
                    cudaMemcpyDeviceToDevice);
    cudaMemcpyAsync(dout + OUTG_ELEMS + KV_ELEMS, past_norm, NORM_ELEMS * sizeof(float),
                    cudaMemcpyDeviceToDevice);

    cudaFuncSetAttribute(fw_kernel, cudaFuncAttributeMaxDynamicSharedMemorySize, SMEM_BYTES);

    dim3 grid(CHUNKS, BH);
    fw_kernel<<<grid, THREADS, SMEM_BYTES>>>(keys, values, queries, outp,
                                             past_kv, past_norm, gates, dout);
}

// round 8
// speedup vs baseline: 1.3642x; 1.1368x over previous
#include <cuda_runtime.h>
#include <cstdint>

// ---------------- problem constants ----------------
#define BB 4
#define HH 16
#define NSEQ 8192
#define DD 64
#define EE 64
#define BH (BB*HH)                       // 64
#define OUTG_ELEMS (BH*NSEQ*EE)          // 33554432
#define KV_ELEMS (BH*DD*EE)              // 262144
#define NORM_ELEMS (BH*DD)               // 4096

#define THREADS 128
// Q path: 64 bh x 64 chunks of 128 rows -> 4096 blocks (one-shot)
#define QBLOCKS 4096
// K path: 64 bh x 32 chunks of 256 rows -> 2048 blocks (4 tiles of 64)
#define KBLOCKS 2048
#define TOTAL_BLOCKS (QBLOCKS + KBLOCKS)  // 6144; every 3rd block is K
#define KTILE 64
#define KNTILES 4

#define STRIDE 68                        // floats per smem row (pad 4 -> conflict-free ldmatrix)
// float offsets inside dynamic smem
#define F_B1  0                          // past_kv^T (tf32) + norm row 64 : 72 rows  (both roles)
#define F_VT  (72*STRIDE)                // K role: v'^T + ones row : 72 rows
#define F_QC  (72*STRIDE)                // Q role: converted Q : 128 rows (aliases VT + start of K bufs)
#define F_K0  (144*STRIDE)               // K role: raw K buf 0 : 64 rows
#define F_K1  (F_K0 + 64*STRIDE)         // K role: raw K buf 1
#define SMEM_FLOATS (F_K1 + 64*STRIDE)   // 272*68 = 18496
#define SMEM_BYTES (SMEM_FLOATS*4)       // 73984 -> 3 blocks/SM

// ---------------- helpers ----------------
__device__ __forceinline__ uint32_t smem_u32(const void* p) {
    uint32_t a;
    asm("{ .reg .u64 t; cvta.to.shared.u64 t, %1; cvt.u32.u64 %0, t; }" : "=r"(a) : "l"(p));
    return a;
}
__device__ __forceinline__ uint32_t cvt_tf32(float x) {
    uint32_t u;
    asm("cvt.rna.tf32.f32 %0, %1;" : "=r"(u) : "f"(x));
    return u;
}
__device__ __forceinline__ float elu1(float x) { return (x > 0.f) ? (x + 1.f) : __expf(x); }
__device__ __forceinline__ void cp16(uint32_t dst, const void* src) {
    asm volatile("cp.async.cg.shared.global [%0], [%1], 16;" :: "r"(dst), "l"(src));
}
__device__ __forceinline__ void mma8(float* d, uint32_t a0, uint32_t a1, uint32_t a2, uint32_t a3,
                                     uint32_t b0, uint32_t b1) {
    asm volatile("mma.sync.aligned.m16n8k8.row.col.f32.tf32.tf32.f32 "
                 "{%0,%1,%2,%3}, {%4,%5,%6,%7}, {%8,%9}, {%0,%1,%2,%3};"
                 : "+f"(d[0]), "+f"(d[1]), "+f"(d[2]), "+f"(d[3])
                 : "r"(a0), "r"(a1), "r"(a2), "r"(a3), "r"(b0), "r"(b1));
}
__device__ __forceinline__ void ldsm4(uint32_t* r, uint32_t addr) {
    asm volatile("ldmatrix.sync.aligned.m8n8.x4.shared.b16 {%0,%1,%2,%3}, [%4];"
                 : "=r"(r[0]), "=r"(r[1]), "=r"(r[2]), "=r"(r[3]) : "r"(addr));
}
__device__ __forceinline__ void ldsm2(uint32_t* r, uint32_t addr) {
    asm volatile("ldmatrix.sync.aligned.m8n8.x2.shared.b16 {%0,%1}, [%2];"
                 : "=r"(r[0]), "=r"(r[1]) : "r"(addr));
}
__device__ __forceinline__ float4 elu_cvt4(float4 v) {
    v.x = __uint_as_float(cvt_tf32(elu1(v.x)));
    v.y = __uint_as_float(cvt_tf32(elu1(v.y)));
    v.z = __uint_as_float(cvt_tf32(elu1(v.z)));
    v.w = __uint_as_float(cvt_tf32(elu1(v.w)));
    return v;
}

__global__ void __launch_bounds__(THREADS, 3)
fw_kernel(const float* __restrict__ keys,
          const float* __restrict__ values,
          const float* __restrict__ queries,
          const float* __restrict__ outp,
          const float* __restrict__ past_kv,
          const float* __restrict__ past_norm,
          const float* __restrict__ head_gates,
          float* __restrict__ dout)
{
    extern __shared__ float smem[];
    const uint32_t sbase = smem_u32(smem);
    const int tid  = threadIdx.x;
    const int lane = tid & 31;
    const int w    = tid >> 5;
    const int x    = blockIdx.x;

    const bool isK = (x % 3) == 0;       // 2048 K blocks interleaved with 4096 Q blocks
    const int kidx = x / 3;
    const int qidx = x - x / 3 - 1;
    const int bh   = isK ? (kidx >> 5) : (qidx >> 6);

    const uint32_t uB1 = sbase + (uint32_t)F_B1 * 4u;
    const uint32_t uVT = sbase + (uint32_t)F_VT * 4u;

    // ---- stage B1 = past_kv^T (tf32) + norm row 64; zero pad rows ----
    {
        const float* pkv = past_kv + (size_t)bh * (DD*EE);
        for (int i = tid; i < DD*EE; i += THREADS) {
            int d = i >> 6, e = i & 63;
            smem[F_B1 + e*STRIDE + d] = __uint_as_float(cvt_tf32(pkv[i]));
        }
        if (tid < 64)
            smem[F_B1 + 64*STRIDE + tid] = __uint_as_float(cvt_tf32(past_norm[bh*DD + tid]));
        for (int i = tid; i < 7*STRIDE; i += THREADS)
            smem[F_B1 + 65*STRIDE + i] = 0.0f;
        if (isK) {
            for (int i = tid; i < 7*STRIDE; i += THREADS)
                smem[F_VT + 65*STRIDE + i] = 0.0f;
            for (int i = tid; i < 64; i += THREADS)
                smem[F_VT + 64*STRIDE + i] = 1.0f;   // ones row -> new_norm column
        }
    }

    float gate;
    {
        float hg = head_gates[bh & (HH-1)];
        gate = 1.0f / (1.0f + __expf(-hg));
    }
    const float omg = 1.0f - gate;

    // ldmatrix lane-address components
    const uint32_t a_row_off = (uint32_t)((lane & 7) + (lane & 8));
    const uint32_t a_col_off = (uint32_t)((lane >> 4) << 2);
    const uint32_t b_n_off   = (uint32_t)(((lane >> 4) << 3) + (lane & 7));
    const uint32_t b_col_off = (uint32_t)(((lane >> 3) & 1) << 2);

    if (!isK) {
        // ================= Q path: one-shot 128 rows =================
        const long rowb = (long)bh * NSEQ + (long)(qidx & 63) * 128;
        const uint32_t uQC = sbase + (uint32_t)F_QC * 4u;

        // load raw Q -> elu+tf32 in regs -> smem (single pass)
        {
            const float4* qs = reinterpret_cast<const float4*>(queries + rowb * DD);
            #pragma unroll
            for (int i = 0; i < 16; ++i) {
                int idx = i*THREADS + tid;
                int row = idx >> 4, seg = idx & 15;
                float4 v = elu_cvt4(qs[idx]);
                *reinterpret_cast<float4*>(smem + F_QC + row*STRIDE + seg*4) = v;
            }
        }
        __syncthreads();

        // GEMM: warp w -> rows 32w..32w+31 (mt=2), N=72
        float d1[2][9][4];
        #pragma unroll
        for (int mt = 0; mt < 2; ++mt)
            #pragma unroll
            for (int n = 0; n < 9; ++n)
                #pragma unroll
                for (int c = 0; c < 4; ++c) d1[mt][n][c] = 0.f;

        #pragma unroll
        for (int ks8 = 0; ks8 < 8; ++ks8) {
            const uint32_t kcol = (uint32_t)(8*ks8);
            uint32_t bf[9][2];
            #pragma unroll
            for (int j = 0; j < 4; ++j) {
                uint32_t r4[4];
                uint32_t n = 16u*j + b_n_off;
                ldsm4(r4, uB1 + (n*STRIDE + kcol + b_col_off)*4u);
                bf[2*j][0] = r4[0]; bf[2*j][1] = r4[1];
                bf[2*j+1][0] = r4[2]; bf[2*j+1][1] = r4[3];
            }
            {
                uint32_t r2[2];
                uint32_t n = 64u + (lane & 7);
                ldsm2(r2, uB1 + (n*STRIDE + kcol + b_col_off)*4u);
                bf[8][0] = r2[0]; bf[8][1] = r2[1];
            }
            #pragma unroll
            for (int mt = 0; mt < 2; ++mt) {
                uint32_t a[4];
                uint32_t row = (uint32_t)(32*w + 16*mt) + a_row_off;
                ldsm4(a, uQC + (row*STRIDE + kcol + a_col_off)*4u);
                #pragma unroll
                for (int nt = 0; nt < 9; ++nt)
                    mma8(d1[mt][nt], a[0], a[1], a[2], a[3], bf[nt][0], bf[nt][1]);
            }
        }

        // epilogue: out_g = out*g + numer*rcp*(1-g)
        #pragma unroll
        for (int mt = 0; mt < 2; ++mt) {
            float den0 = __shfl_sync(0xffffffffu, d1[mt][8][0], lane & 28);
            float den1 = __shfl_sync(0xffffffffu, d1[mt][8][2], lane & 28);
            float c0 = (1.0f / fmaxf(den0, 1e-10f)) * omg;
            float c1 = (1.0f / fmaxf(den1, 1e-10f)) * omg;
            int lrow = 32*w + 16*mt + (lane >> 2);
            int ec = lane & 3;
            const float2* o0 = (const float2*)(outp + (size_t)(rowb + lrow) * EE);
            const float2* o1 = (const float2*)(outp + (size_t)(rowb + lrow + 8) * EE);
            float2* g0 = (float2*)(dout + (size_t)(rowb + lrow) * EE);
            float2* g1 = (float2*)(dout + (size_t)(rowb + lrow + 8) * EE);
            #pragma unroll
            for (int nt = 0; nt < 8; ++nt) {
                float2 a = o0[4*nt + ec];
                float2 b = o1[4*nt + ec];
                float2 ra, rb;
                ra.x = a.x * gate + d1[mt][nt][0] * c0;
                ra.y = a.y * gate + d1[mt][nt][1] * c0;
                rb.x = b.x * gate + d1[mt][nt][2] * c1;
                rb.y = b.y * gate + d1[mt][nt][3] * c1;
                g0[4*nt + ec] = ra;
                g1[4*nt + ec] = rb;
            }
        }
        return;
    }

    // ================= K path: 256 rows, 4 tiles, delta-rule chain =================
    const long rowbase = (long)bh * NSEQ + (long)(kidx & 31) * 256;

    auto stageK = [&](int buf, long rowb) {
        const float* ks = keys + rowb * DD;
        uint32_t kd = sbase + (uint32_t)(buf ? F_K1 : F_K0) * 4u;
        #pragma unroll
        for (int j = 0; j < 8; ++j) {
            int idx = j*THREADS + tid;
            int row = idx >> 4, seg = idx & 15;
            cp16(kd + (uint32_t)row*(STRIDE*4) + seg*16, ks + row*DD + seg*4);
        }
        asm volatile("cp.async.commit_group;" ::: "memory");
    };

    stageK(0, rowbase);

    float d2[9][4];
    #pragma unroll
    for (int n = 0; n < 9; ++n)
        #pragma unroll
        for (int c = 0; c < 4; ++c) d2[n][c] = 0.f;

    for (int t = 0; t < KNTILES; ++t) {
        const long rowb = rowbase + (long)t * KTILE;
        if (t + 1 < KNTILES) {
            stageK((t+1) & 1, rowb + KTILE);
            asm volatile("cp.async.wait_group 1;" ::: "memory");
        } else {
            asm volatile("cp.async.wait_group 0;" ::: "memory");
        }
        __syncthreads();

        float* kc = smem + ((t & 1) ? F_K1 : F_K0);
        const uint32_t uKC = sbase + (uint32_t)((t & 1) ? F_K1 : F_K0) * 4u;

        // convert K in place (elu+tf32 once; read by GEMM1 and GEMM2^T)
        #pragma unroll
        for (int j = 0; j < 8; ++j) {
            int idx = j*THREADS + tid;
            int row = idx >> 4, seg = idx & 15;
            float4* p = reinterpret_cast<float4*>(kc + row*STRIDE + seg*4);
            *p = elu_cvt4(*p);
        }
        __syncthreads();

        // GEMM1-K: M=64 (warp w -> rows 16w..16w+15), N=72
        float d1[9][4];
        #pragma unroll
        for (int n = 0; n < 9; ++n)
            #pragma unroll
            for (int c = 0; c < 4; ++c) d1[n][c] = 0.f;

        #pragma unroll
        for (int ks8 = 0; ks8 < 8; ++ks8) {
            const uint32_t kcol = (uint32_t)(8*ks8);
            uint32_t bf[9][2];
            #pragma unroll
            for (int j = 0; j < 4; ++j) {
                uint32_t r4[4];
                uint32_t n = 16u*j + b_n_off;
                ldsm4(r4, uB1 + (n*STRIDE + kcol + b_col_off)*4u);
                bf[2*j][0] = r4[0]; bf[2*j][1] = r4[1];
                bf[2*j+1][0] = r4[2]; bf[2*j+1][1] = r4[3];
            }
            {
                uint32_t r2[2];
                uint32_t n = 64u + (lane & 7);
                ldsm2(r2, uB1 + (n*STRIDE + kcol + b_col_off)*4u);
                bf[8][0] = r2[0]; bf[8][1] = r2[1];
            }
            uint32_t a[4];
            uint32_t row = (uint32_t)(16*w) + a_row_off;
            ldsm4(a, uKC + (row*STRIDE + kcol + a_col_off)*4u);
            #pragma unroll
            for (int nt = 0; nt < 9; ++nt)
                mma8(d1[nt], a[0], a[1], a[2], a[3], bf[nt][0], bf[nt][1]);
        }

        // epilogue: v' = values - numer*rcp -> VT (transposed, tf32)
        {
            float den0 = __shfl_sync(0xffffffffu, d1[8][0], lane & 28);
            float den1 = __shfl_sync(0xffffffffu, d1[8][2], lane & 28);
            float r0 = 1.0f / fmaxf(den0, 1e-10f);
            float r1 = 1.0f / fmaxf(den1, 1e-10f);
            int lrow = 16*w + (lane >> 2);
            int ec = lane & 3;
            const float2* v0 = (const float2*)(values + (size_t)(rowb + lrow) * EE);
            const float2* v1 = (const float2*)(values + (size_t)(rowb + lrow + 8) * EE);
            #pragma unroll
            for (int nt = 0; nt < 8; ++nt) {
                float2 a = v0[4*nt + ec];
                float2 b = v1[4*nt + ec];
                int e = 8*nt + 2*ec;
                float p00 = a.x - d1[nt][0] * r0;
                float p01 = a.y - d1[nt][1] * r0;
                float p10 = b.x - d1[nt][2] * r1;
                float p11 = b.y - d1[nt][3] * r1;
                smem[F_VT + e*STRIDE + lrow]         = __uint_as_float(cvt_tf32(p00));
                smem[F_VT + (e+1)*STRIDE + lrow]     = __uint_as_float(cvt_tf32(p01));
                smem[F_VT + e*STRIDE + lrow + 8]     = __uint_as_float(cvt_tf32(p10));
                smem[F_VT + (e+1)*STRIDE + lrow + 8] = __uint_as_float(cvt_tf32(p11));
            }
        }
        __syncthreads();

        // GEMM2: D2 += k^T x v'  (N=72, col 64 = norm sums)
        #pragma unroll
        for (int ks8 = 0; ks8 < 8; ++ks8) {
            const uint32_t kcol = (uint32_t)(8*ks8);
            uint32_t bf[9][2];
            #pragma unroll
            for (int j = 0; j < 4; ++j) {
                uint32_t r4[4];
                uint32_t n = 16u*j + b_n_off;
                ldsm4(r4, uVT + (n*STRIDE + kcol + b_col_off)*4u);
                bf[2*j][0] = r4[0]; bf[2*j][1] = r4[1];
                bf[2*j+1][0] = r4[2]; bf[2*j+1][1] = r4[3];
            }
            {
                uint32_t r2[2];
                uint32_t n = 64u + (lane & 7);
                ldsm2(r2, uVT + (n*STRIDE + kcol + b_col_off)*4u);
                bf[8][0] = r2[0]; bf[8][1] = r2[1];
            }
            // A = converted k^T : scalar transposed reads (conflict-free stride-68)
            const float* ap = kc + (8*ks8 + (lane&3))*STRIDE + 16*w + (lane>>2);
            uint32_t a0 = __float_as_uint(ap[0]);
            uint32_t a1 = __float_as_uint(ap[8]);
            uint32_t a2 = __float_as_uint(ap[4*STRIDE]);
            uint32_t a3 = __float_as_uint(ap[4*STRIDE + 8]);
            #pragma unroll
            for (int nt = 0; nt < 9; ++nt)
                mma8(d2[nt], a0, a1, a2, a3, bf[nt][0], bf[nt][1]);
        }
        __syncthreads();
    }

    // ---- flush D2: new_kv (+past via memcpy seed) and new_norm ----
    {
        float* okv = dout + OUTG_ELEMS + (size_t)bh * (DD*EE);
        int dr = 16*w + (lane >> 2);
        #pragma unroll
        for (int nt = 0; nt < 8; ++nt) {
            int e = 8*nt + 2*(lane & 3);
            atomicAdd(okv + dr*EE + e,        d2[nt][0]);
            atomicAdd(okv + dr*EE + e + 1,    d2[nt][1]);
            atomicAdd(okv + (dr+8)*EE + e,    d2[nt][2]);
            atomicAdd(okv + (dr+8)*EE + e+1,  d2[nt][3]);
        }
        if ((lane & 3) == 0) {
            float* on = dout + OUTG_ELEMS + KV_ELEMS + bh*DD;
            atomicAdd(on + dr,     d2[8][0]);
            atomicAdd(on + dr + 8, d2[8][2]);
        }
    }
}

extern "C" void kernel_launch(void* const* d_in, const int* in_sizes, int n_in,
                              void* d_out, int out_size)
{
    const float* keys      = (const float*)d_in[0];
    const float* values    = (const float*)d_in[1];
    const float* queries   = (const float*)d_in[2];
    const float* outp      = (const float*)d_in[3];
    const float* past_kv   = (const float*)d_in[4];
    const float* past_norm = (const float*)d_in[5];
    const float* gates     = (const float*)d_in[6];
    float* dout = (float*)d_out;

    // Seed new_kv / new_norm output regions (atomics add partials on top)
    cudaMemcpyAsync(dout + OUTG_ELEMS, past_kv, KV_ELEMS * sizeof(float),
                    cudaMemcpyDeviceToDevice);
    cudaMemcpyAsync(dout + OUTG_ELEMS + KV_ELEMS, past_norm, NORM_ELEMS * sizeof(float),
                    cudaMemcpyDeviceToDevice);

    cudaFuncSetAttribute(fw_kernel, cudaFuncAttributeMaxDynamicSharedMemorySize, SMEM_BYTES);

    fw_kernel<<<TOTAL_BLOCKS, THREADS, SMEM_BYTES>>>(keys, values, queries, outp,
                                                     past_kv, past_norm, gates, dout);
}